// round 14
// baseline (speedup 1.0000x reference)
#include <cuda_runtime.h>
#include <cuda_fp16.h>
#include <math.h>
#include <stdint.h>

#define N_SEQ   256
#define T_LEN   128
#define EMBED   512
#define UNITS   512
#define GATEC   2048
#define M_ALL   (N_SEQ * T_LEN)

// rec smem: B (U fp16) 64KB + A (h fp16) 3 x 16KB
#define SM_B     0
#define SM_A     65536
#define SMEM_REC (SM_A + 3 * 16384)      // 114688 B
// xw smem: 2 bufs x (A 16KB + B 16KB)
#define XW_BUF   32768
#define SMEM_XW  (2 * XW_BUF)            // 65536 B

#define SWZ(o) ((o) ^ (((o) >> 3) & 0x70))

// ---------------- PTX helpers (plain-sm_103-legal only) ---------------------
__device__ __forceinline__ uint32_t s2u(const void* p) {
    uint32_t a;
    asm("{ .reg .u64 t; cvta.to.shared.u64 t, %1; cvt.u32.u64 %0, t; }"
        : "=r"(a) : "l"(p));
    return a;
}
__device__ __forceinline__ void cpasync16(uint32_t dst, const void* src) {
    asm volatile("cp.async.cg.shared.global [%0], [%1], 16;" :: "r"(dst), "l"(src));
}
__device__ __forceinline__ void cpcommit() { asm volatile("cp.async.commit_group;"); }
template <int N> __device__ __forceinline__ void cpwait() {
    asm volatile("cp.async.wait_group %0;" :: "n"(N));
}
__device__ __forceinline__ void ldsm4(uint32_t* r, uint32_t addr) {
    asm volatile("ldmatrix.sync.aligned.m8n8.x4.shared.b16 {%0,%1,%2,%3}, [%4];"
        : "=r"(r[0]), "=r"(r[1]), "=r"(r[2]), "=r"(r[3]) : "r"(addr));
}
__device__ __forceinline__ void mma16816(float* c, const uint32_t* a, const uint32_t* b) {
    asm volatile(
        "mma.sync.aligned.m16n8k16.row.col.f32.f16.f16.f32 "
        "{%0,%1,%2,%3}, {%4,%5,%6,%7}, {%8,%9}, {%0,%1,%2,%3};"
        : "+f"(c[0]), "+f"(c[1]), "+f"(c[2]), "+f"(c[3])
        : "r"(a[0]), "r"(a[1]), "r"(a[2]), "r"(a[3]), "r"(b[0]), "r"(b[1]));
}
// A fragment m16xk16 row-major: rows mb.., k-bytes kb within 128B rows
__device__ __forceinline__ void ldA16(uint32_t* r, uint32_t tile, int mb, int kb, int lane) {
    uint32_t o = (uint32_t)((mb + (lane & 15)) * 128 + kb + ((lane >> 4) << 4));
    ldsm4(r, tile + SWZ(o));
}
// B fragments: two n8 tiles (rows nb..nb+15 of [n][k] layout)
__device__ __forceinline__ void ldB16(uint32_t* r, uint32_t tile, int nb, int kb, int lane) {
    uint32_t o = (uint32_t)((nb + ((lane >> 4) << 3) + (lane & 7)) * 128 + kb
                            + (((lane >> 3) & 1) << 4));
    ldsm4(r, tile + SWZ(o));
}

// ---------------- scratch ---------------------------------------------------
__device__ float    g_xW[2][M_ALL][GATEC];        // natural layout x@W + b
__device__ __half   g_Upk[2][GATEC][UNITS];       // [dir][packed n][k] fp16
__device__ __half   g_Wpk[2][GATEC][EMBED];       // [dir][n][k] fp16
__device__ __half   g_Asp[M_ALL][EMBED];          // gathered emb fp16
__device__ __half   g_hsp[2][2][N_SEQ][UNITS];    // [dir][parity][n][u] fp16
__device__ unsigned g_barp[4 * 32];               // padded per-group barriers

// packed col p: j=p>>3, q=(p>>1)&3, e=p&1 -> unit=(j>>1)*4+q, gate=(j&1)*2+e

// ---------------- init ------------------------------------------------------
__global__ void init_kernel()
{
    int i = blockIdx.x * 256 + threadIdx.x;
    if (i < 128) g_barp[i] = 0;
    if (i < 2 * N_SEQ * UNITS) {
        int dir = i / (N_SEQ * UNITS);
        int off = i % (N_SEQ * UNITS);
        (&g_hsp[dir][0][0][0])[off] = __float2half(0.0f);
    }
}

// ---------------- U (permuted) + W pack: fp32 -> fp16 -----------------------
__global__ void pack_kernel(const float* __restrict__ Uf, const float* __restrict__ Ub,
                            const float* __restrict__ Wf, const float* __restrict__ Wb)
{
    int i     = blockIdx.x * 256 + threadIdx.x;   // over 2048*512
    int dir   = blockIdx.y;
    int which = blockIdx.z;                       // 0: U, 1: W
    if (i >= GATEC * 512) return;
    int P = i >> 9, k = i & 511;
    float v;
    if (which == 0) {
        int nt = P >> 6, p = P & 63;
        int j = p >> 3, q = (p >> 1) & 3, e = p & 1;
        int unit = nt * 16 + (j >> 1) * 4 + q;
        int gate = (j & 1) * 2 + e;
        const float* U = dir ? Ub : Uf;
        v = U[(size_t)k * GATEC + gate * UNITS + unit];
        g_Upk[dir][P][k] = __float2half(v);
    } else {
        const float* W = dir ? Wb : Wf;
        v = W[(size_t)k * GATEC + P];
        g_Wpk[dir][P][k] = __float2half(v);
    }
}

// ---------------- A pack: gather emb rows -> fp16 ---------------------------
__global__ void apack_kernel(const int* __restrict__ x, const float* __restrict__ emb)
{
    const int m  = blockIdx.x;
    const int k2 = threadIdx.x;                   // 0..255 pairs
    const int id = x[m];
    float2 v = *(const float2*)(emb + (size_t)id * EMBED + k2 * 2);
    *(__half2*)&g_Asp[m][k2 * 2] = __floats2half2_rn(v.x, v.y);
}

// ---------------- input projection via single-pass fp16 HMMA ----------------
__global__ void __launch_bounds__(256, 2)
xw_hmma(const float* __restrict__ bf_, const float* __restrict__ bb_)
{
    extern __shared__ __align__(1024) char smem[];
    const uint32_t sb = s2u(smem);

    const int tid  = threadIdx.x;
    const int wid  = tid >> 5;
    const int lane = tid & 31;
    const int nt   = blockIdx.x;                  // 0..15
    const int mt   = blockIdx.y;                  // 0..255
    const int dir  = blockIdx.z;
    const int m0   = mt * 128;
    const int n0   = nt * 128;
    const float* __restrict__ bias = dir ? bb_ : bf_;

    const int mg = wid & 3;                       // warp m-group (32 rows)
    const int ng = wid >> 2;                      // warp n-group (64 cols)

    auto fill = [&](int b, int kc) {
#pragma unroll
        for (int j = 0; j < 8; j++) {
            int i    = tid + j * 256;             // 0..2047
            int reg  = i >> 10;                   // 0:A 1:B
            int idx  = i & 1023;
            int r    = idx >> 3;
            int seg  = idx & 7;
            const void* src = (reg == 0)
                ? (const void*)&g_Asp[m0 + r][kc * 64 + seg * 8]
                : (const void*)&g_Wpk[dir][n0 + r][kc * 64 + seg * 8];
            uint32_t dst = sb + (uint32_t)b * XW_BUF + (uint32_t)reg * 16384
                         + SWZ((uint32_t)(r * 128 + seg * 16));
            cpasync16(dst, src);
        }
        cpcommit();
    };

    float acc[2][8][4];
#pragma unroll
    for (int a = 0; a < 2; a++)
#pragma unroll
        for (int j = 0; j < 8; j++)
#pragma unroll
            for (int c = 0; c < 4; c++) acc[a][j][c] = 0.0f;

    fill(0, 0);
    fill(1, 1);

    for (int kc = 0; kc < 8; kc++) {
        const int b = kc & 1;
        if (kc < 7) cpwait<1>(); else cpwait<0>();
        __syncthreads();

        const uint32_t aT = sb + (uint32_t)b * XW_BUF;
        const uint32_t bT = aT + 16384;

#pragma unroll
        for (int kk = 0; kk < 4; kk++) {
            const int kb = kk * 32;
            uint32_t af[2][4], bfr[4][4];
            ldA16(af[0], aT, mg * 32,      kb, lane);
            ldA16(af[1], aT, mg * 32 + 16, kb, lane);
#pragma unroll
            for (int p4 = 0; p4 < 4; p4++)
                ldB16(bfr[p4], bT, ng * 64 + p4 * 16, kb, lane);
#pragma unroll
            for (int a = 0; a < 2; a++)
#pragma unroll
                for (int j = 0; j < 8; j++)
                    mma16816(acc[a][j], af[a], &bfr[j >> 1][(j & 1) * 2]);
        }

        __syncthreads();
        if (kc + 2 < 8) fill(b, kc + 2);
    }

    // epilogue: add bias, store natural layout (coalesced float2)
#pragma unroll
    for (int j = 0; j < 8; j++) {
        const int col = n0 + ng * 64 + j * 8 + (lane & 3) * 2;
        const float2 bv = *(const float2*)(bias + col);
#pragma unroll
        for (int a = 0; a < 2; a++) {
            const int r0 = m0 + mg * 32 + a * 16 + (lane >> 2);
            float2 o0, o1;
            o0.x = acc[a][j][0] + bv.x;
            o0.y = acc[a][j][1] + bv.y;
            o1.x = acc[a][j][2] + bv.x;
            o1.y = acc[a][j][3] + bv.y;
            *(float2*)&g_xW[dir][r0][col]     = o0;
            *(float2*)&g_xW[dir][r0 + 8][col] = o1;
        }
    }
}

// ---------------- persistent single-pass fp16 HMMA recurrence ---------------
__device__ __forceinline__ float sigmoidf_(float v) { return 1.0f / (1.0f + expf(-v)); }

__global__ void __launch_bounds__(256, 1)
rec_kernel(const int* __restrict__ x, float* __restrict__ out)
{
    extern __shared__ __align__(1024) char smem[];
    const uint32_t sb = s2u(smem);

    const int tid  = threadIdx.x;
    const int wid  = tid >> 5;
    const int lane = tid & 31;
    const int bid  = blockIdx.x;
    const int dir  = bid >> 6;
    const int mt   = (bid >> 5) & 1;
    const int nt   = bid & 31;
    const int grp  = bid >> 5;
    const int m0   = mt * 128;
    const int wb   = wid * 16;

    // ---- one-time B (U) preload: 8 K-chunks --------------------------------
    for (int i = tid; i < 4096; i += 256) {
        int kc   = (i >> 9) & 7;
        int P    = (i >> 3) & 63;
        int seg  = i & 7;
        const void* src = &g_Upk[dir][nt * 64 + P][kc * 64 + seg * 8];
        uint32_t dst = sb + SM_B + (uint32_t)kc * 8192
                     + SWZ((uint32_t)(P * 128 + seg * 16));
        cpasync16(dst, src);
    }
    cpcommit();

    float c_reg[8], h_reg[8];
#pragma unroll
    for (int s = 0; s < 8; s++) { c_reg[s] = 0.0f; h_reg[s] = 0.0f; }
    unsigned barcnt = 0;

    auto fillA = [&](int b, int kc, int pin) {
#pragma unroll
        for (int j = 0; j < 4; j++) {
            int i   = tid + j * 256;              // 0..1023
            int r   = i >> 3;
            int seg = i & 7;
            const void* src = &g_hsp[dir][pin][m0 + r][kc * 64 + seg * 8];
            uint32_t dst = sb + SM_A + (uint32_t)b * 16384
                         + SWZ((uint32_t)(r * 128 + seg * 16));
            cpasync16(dst, src);
        }
        cpcommit();
    };

    auto gbar = [&]() {
        __syncthreads();
        barcnt++;
        if (tid == 0) {
            unsigned* ctr = &g_barp[grp * 32];
            const unsigned target = barcnt * 32;
            asm volatile("red.release.gpu.add.u32 [%0], 1;" :: "l"(ctr) : "memory");
            unsigned v;
            while (true) {
                asm volatile("ld.acquire.gpu.u32 %0, [%1];" : "=r"(v) : "l"(ctr) : "memory");
                if (v >= target) break;
                __nanosleep(32);
            }
        }
        __syncthreads();
    };

    const int rA = lane >> 2;
    const int cq = lane & 3;

    for (int t = 0; t < T_LEN; t++) {
        const int pin  = t & 1;
        const int pout = pin ^ 1;
        const int tt   = dir ? (T_LEN - 1 - t) : t;

        // prefetch h tiles first so cp.async overlaps the scattered LDGs below
        fillA(0, 0, pin);
        fillA(1, 1, pin);
        fillA(2, 2, pin);

        const int n0r   = m0 + wb + rA;
        const int row0  = n0r * T_LEN + tt;
        const int row1  = (n0r + 8) * T_LEN + tt;
        const int msk0  = x[row0];
        const int msk1  = x[row1];
        float xwv[2][4][4];
#pragma unroll
        for (int rh = 0; rh < 2; rh++) {
            const float* base = &g_xW[dir][rh ? row1 : row0][nt * 16 + cq];
#pragma unroll
            for (int uu = 0; uu < 4; uu++)
#pragma unroll
                for (int g = 0; g < 4; g++)
                    xwv[rh][uu][g] = base[g * UNITS + uu * 4];
        }

        float acc[8][4];
#pragma unroll
        for (int j = 0; j < 8; j++)
#pragma unroll
            for (int c = 0; c < 4; c++) acc[j][c] = 0.0f;

        for (int kc = 0; kc < 8; kc++) {
            if (kc < 6) cpwait<2>();
            else if (kc == 6) cpwait<1>();
            else cpwait<0>();
            __syncthreads();

            const uint32_t aT = sb + SM_A + (uint32_t)(kc % 3) * 16384;
            const uint32_t bT = sb + SM_B + (uint32_t)kc * 8192;

#pragma unroll
            for (int kk = 0; kk < 4; kk++) {
                const int kb = kk * 32;
                uint32_t af[4], bfr[4][4];
                ldA16(af, aT, wb, kb, lane);
#pragma unroll
                for (int p4 = 0; p4 < 4; p4++)
                    ldB16(bfr[p4], bT, p4 * 16, kb, lane);
#pragma unroll
                for (int j = 0; j < 8; j++)
                    mma16816(acc[j], af, &bfr[j >> 1][(j & 1) * 2]);
            }

            __syncthreads();
            if (kc + 3 < 8) fillA(kc % 3, kc + 3, pin);
        }

        // ---- gate math + masked update; lane owns 2 rows x 4 units ---------
#pragma unroll
        for (int rh = 0; rh < 2; rh++) {
            const int n    = n0r + rh * 8;
            const bool msk = (rh ? msk1 : msk0) != 0;
#pragma unroll
            for (int uu = 0; uu < 4; uu++) {
                const float zi = xwv[rh][uu][0] + acc[uu * 2 + 0][rh * 2 + 0];
                const float zf = xwv[rh][uu][1] + acc[uu * 2 + 0][rh * 2 + 1];
                const float zg = xwv[rh][uu][2] + acc[uu * 2 + 1][rh * 2 + 0];
                const float zo = xwv[rh][uu][3] + acc[uu * 2 + 1][rh * 2 + 1];
                const int s = rh * 4 + uu;
                float ig = sigmoidf_(zi), fg = sigmoidf_(zf);
                float gg = tanhf(zg),     og = sigmoidf_(zo);
                float cn = fmaf(fg, c_reg[s], ig * gg);
                float hn = og * tanhf(cn);
                if (!msk) { cn = c_reg[s]; hn = h_reg[s]; }
                c_reg[s] = cn;
                h_reg[s] = hn;
                const int gu = nt * 16 + uu * 4 + cq;
                g_hsp[dir][pout][n][gu] = __float2half(hn);
            }
        }

        if (t < T_LEN - 1) gbar();
    }

    // ---- final output: concat(h_fwd, h_bwd), straight from registers -------
#pragma unroll
    for (int rh = 0; rh < 2; rh++) {
        const int n = m0 + wb + rA + rh * 8;
#pragma unroll
        for (int uu = 0; uu < 4; uu++) {
            const int gu = nt * 16 + uu * 4 + cq;
            out[(size_t)n * 1024 + dir * 512 + gu] = h_reg[rh * 4 + uu];
        }
    }
}

// ---------------- launch ----------------------------------------------------
extern "C" void kernel_launch(void* const* d_in, const int* in_sizes, int n_in,
                              void* d_out, int out_size)
{
    const int*   x   = (const int*)  d_in[0];
    const float* emb = (const float*)d_in[1];
    const float* Wf  = (const float*)d_in[2];
    const float* Uf  = (const float*)d_in[3];
    const float* bf  = (const float*)d_in[4];
    const float* Wb  = (const float*)d_in[5];
    const float* Ub  = (const float*)d_in[6];
    const float* bb  = (const float*)d_in[7];
    float* out = (float*)d_out;
    (void)in_sizes; (void)n_in; (void)out_size;

    cudaFuncSetAttribute(rec_kernel,
                         cudaFuncAttributeMaxDynamicSharedMemorySize, SMEM_REC);
    cudaFuncSetAttribute(xw_hmma,
                         cudaFuncAttributeMaxDynamicSharedMemorySize, SMEM_XW);

    init_kernel<<<1024, 256>>>();
    pack_kernel<<<dim3(4096, 2, 2), 256>>>(Uf, Ub, Wf, Wb);
    apack_kernel<<<M_ALL, 256>>>(x, emb);

    dim3 gx(16, 256, 2);
    xw_hmma<<<gx, 256, SMEM_XW>>>(bf, bb);

    rec_kernel<<<128, 256, SMEM_REC>>>(x, out);
}